// round 2
// baseline (speedup 1.0000x reference)
#include <cuda_runtime.h>
#include <math.h>

#define NTHREADS 256
#define MROWS    64
#define XLD      516      // x row stride in smem floats (16B-aligned rows, conflict-free)
#define H1LD     132
#define H2LD     68
#define H3LD     36

// ---- shared memory layout (float offsets) ----
#define X_OFF     0
#define WBUF_OFF  (MROWS * XLD)            // 33024 ; 4096-float staging buffer
#define H1_OFF    (WBUF_OFF + 4096)        // 37120
#define LIN_OFF   (H1_OFF + MROWS * H1LD)  // 45568
#define FM2_OFF   (LIN_OFF + MROWS)
#define LINW_OFF  (FM2_OFF + MROWS)
#define WO_OFF    (LINW_OFF + 512)
#define SMEM_FLOATS (WO_OFF + 32)          // 46240 floats = 184960 bytes
// overlay inside the X region once FM is done with x:
#define W2_OFF    0                        // 128*64 = 8192 floats
#define H2_OFF    8192                     // 64*68  = 4352
#define W3_OFF    (H2_OFF + MROWS * H2LD)  // 12544 ; 64*32 = 2048
#define H3_OFF    (W3_OFF + 2048)          // 14592 ; 64*36 = 2304 -> ends 16896 < 33024

extern __shared__ float sm[];

__global__ __launch_bounds__(NTHREADS, 1)
void deepfm_fused_kernel(
    const float* __restrict__ x,     const float* __restrict__ fm_w,
    const float* __restrict__ fm_b,  const float* __restrict__ lin_w,
    const float* __restrict__ lin_b, const float* __restrict__ w1,
    const float* __restrict__ b1,    const float* __restrict__ w2,
    const float* __restrict__ b2,    const float* __restrict__ w3,
    const float* __restrict__ b3,    const float* __restrict__ wo,
    const float* __restrict__ bo,    const float* __restrict__ bias,
    float* __restrict__ out)
{
    const int tid = threadIdx.x;
    const int r0  = blockIdx.x * MROWS;

    // ---------------- load x tile [64][512] into smem (coalesced float4) ----------------
    {
        const float4* gx = (const float4*)(x + (size_t)r0 * 512);
        #pragma unroll
        for (int l = 0; l < 32; l++) {
            int idx = tid + l * NTHREADS;          // idx in [0, 64*128)
            int row = idx >> 7;
            int c4  = idx & 127;
            float4 v = gx[row * 128 + c4];
            *(float4*)&sm[X_OFF + row * XLD + c4 * 4] = v;
        }
    }
    // lin_w (512 floats) and wo (32 floats)
    if (tid < 128) {
        *(float4*)&sm[LINW_OFF + tid * 4] = ((const float4*)lin_w)[tid];
    } else if (tid < 136) {
        *(float4*)&sm[WO_OFF + (tid - 128) * 4] = ((const float4*)wo)[tid - 128];
    }
    __syncthreads();

    // ---------------- Phase 1: h1 = relu(x @ W1 + b1)  [64,512]@[512,128] ----------------
    {
        const int rg = tid >> 4;        // 16 row groups of 4 rows
        const int cg = tid & 15;        // 16 col groups of 8 cols
        const int rbase = rg * 4;
        const int cbase = cg * 8;

        float acc[4][8];
        #pragma unroll
        for (int i = 0; i < 4; i++)
            #pragma unroll
            for (int j = 0; j < 8; j++) acc[i][j] = 0.f;

        for (int k0 = 0; k0 < 512; k0 += 32) {
            __syncthreads();   // protect wbuf before overwrite
            // stage w1[k0:k0+32, 0:128] -> wbuf (1024 float4s)
            const float4* gw = (const float4*)(w1 + k0 * 128);
            #pragma unroll
            for (int l = 0; l < 4; l++) {
                int idx = tid + l * NTHREADS;
                *(float4*)&sm[WBUF_OFF + idx * 4] = gw[idx];
            }
            __syncthreads();

            #pragma unroll
            for (int kk = 0; kk < 32; kk += 4) {
                float xs[4][4];
                #pragma unroll
                for (int i = 0; i < 4; i++) {
                    float4 v = *(const float4*)&sm[X_OFF + (rbase + i) * XLD + k0 + kk];
                    xs[i][0] = v.x; xs[i][1] = v.y; xs[i][2] = v.z; xs[i][3] = v.w;
                }
                #pragma unroll
                for (int q = 0; q < 4; q++) {
                    const float* wrow = &sm[WBUF_OFF + (kk + q) * 128 + cbase];
                    float4 wa = *(const float4*)(wrow);
                    float4 wb = *(const float4*)(wrow + 4);
                    #pragma unroll
                    for (int i = 0; i < 4; i++) {
                        float xq = xs[i][q];
                        acc[i][0] = fmaf(xq, wa.x, acc[i][0]);
                        acc[i][1] = fmaf(xq, wa.y, acc[i][1]);
                        acc[i][2] = fmaf(xq, wa.z, acc[i][2]);
                        acc[i][3] = fmaf(xq, wa.w, acc[i][3]);
                        acc[i][4] = fmaf(xq, wb.x, acc[i][4]);
                        acc[i][5] = fmaf(xq, wb.y, acc[i][5]);
                        acc[i][6] = fmaf(xq, wb.z, acc[i][6]);
                        acc[i][7] = fmaf(xq, wb.w, acc[i][7]);
                    }
                }
            }
        }
        // epilogue: + b1, relu, store to h1
        float bb[8];
        #pragma unroll
        for (int j = 0; j < 8; j++) bb[j] = __ldg(&b1[cbase + j]);
        #pragma unroll
        for (int i = 0; i < 4; i++) {
            float4 o0, o1;
            o0.x = fmaxf(acc[i][0] + bb[0], 0.f);
            o0.y = fmaxf(acc[i][1] + bb[1], 0.f);
            o0.z = fmaxf(acc[i][2] + bb[2], 0.f);
            o0.w = fmaxf(acc[i][3] + bb[3], 0.f);
            o1.x = fmaxf(acc[i][4] + bb[4], 0.f);
            o1.y = fmaxf(acc[i][5] + bb[5], 0.f);
            o1.z = fmaxf(acc[i][6] + bb[6], 0.f);
            o1.w = fmaxf(acc[i][7] + bb[7], 0.f);
            *(float4*)&sm[H1_OFF + (rbase + i) * H1LD + cbase]     = o0;
            *(float4*)&sm[H1_OFF + (rbase + i) * H1LD + cbase + 4] = o1;
        }
    }

    // ---------------- FM phase (reuses x tile; streams fm_w/fm_b in 128-k chunks) ---------
    {
        const int row = tid >> 2;       // 64 rows
        const int dg  = tid & 3;        // 4 groups of 4 d's
        float s_sum[4] = {0.f, 0.f, 0.f, 0.f};
        float s_b[4]   = {0.f, 0.f, 0.f, 0.f};
        float s_sq[4]  = {0.f, 0.f, 0.f, 0.f};
        float s_lin    = 0.f;

        for (int k0 = 0; k0 < 512; k0 += 128) {
            __syncthreads();   // wbuf reuse (also orders vs phase-1 readers)
            const float4* gwa = (const float4*)(fm_w + k0 * 16);
            const float4* gwb = (const float4*)(fm_b + k0 * 16);
            #pragma unroll
            for (int l = 0; l < 2; l++) {
                int idx = tid + l * NTHREADS;      // [0, 512) float4s
                *(float4*)&sm[WBUF_OFF + idx * 4]        = gwa[idx];
                *(float4*)&sm[WBUF_OFF + 2048 + idx * 4] = gwb[idx];
            }
            __syncthreads();

            #pragma unroll 4
            for (int kk = 0; kk < 128; kk++) {
                float xv = sm[X_OFF + row * XLD + k0 + kk];
                float4 a = *(const float4*)&sm[WBUF_OFF + kk * 16 + dg * 4];
                float4 b = *(const float4*)&sm[WBUF_OFF + 2048 + kk * 16 + dg * 4];
                s_sum[0] = fmaf(xv, a.x, s_sum[0]);
                s_sum[1] = fmaf(xv, a.y, s_sum[1]);
                s_sum[2] = fmaf(xv, a.z, s_sum[2]);
                s_sum[3] = fmaf(xv, a.w, s_sum[3]);
                s_b[0] += b.x; s_b[1] += b.y; s_b[2] += b.z; s_b[3] += b.w;
                float t0 = fmaf(xv, a.x, b.x);
                float t1 = fmaf(xv, a.y, b.y);
                float t2 = fmaf(xv, a.z, b.z);
                float t3 = fmaf(xv, a.w, b.w);
                s_sq[0] = fmaf(t0, t0, s_sq[0]);
                s_sq[1] = fmaf(t1, t1, s_sq[1]);
                s_sq[2] = fmaf(t2, t2, s_sq[2]);
                s_sq[3] = fmaf(t3, t3, s_sq[3]);
                if (dg == 0) s_lin = fmaf(xv, sm[LINW_OFF + k0 + kk], s_lin);
            }
        }
        // per-thread combine over its 4 d's, then reduce across the 4 lanes of the row
        float v = 0.f;
        #pragma unroll
        for (int j = 0; j < 4; j++) {
            float se = s_sum[j] + s_b[j];
            v += se * se - s_sq[j];
        }
        v += __shfl_xor_sync(0xffffffffu, v, 1);
        v += __shfl_xor_sync(0xffffffffu, v, 2);
        if (dg == 0) {
            sm[FM2_OFF + row] = 0.5f * v;
            sm[LIN_OFF + row] = s_lin;
        }
    }
    __syncthreads();    // FM done reading x region; h1 fully written

    // ---------------- load W2 (whole, 8192 f) and W3 (2048 f) into x region ----------------
    {
        const float4* g2 = (const float4*)w2;
        #pragma unroll
        for (int l = 0; l < 8; l++) {
            int idx = tid + l * NTHREADS;
            *(float4*)&sm[W2_OFF + idx * 4] = g2[idx];
        }
        const float4* g3 = (const float4*)w3;
        #pragma unroll
        for (int l = 0; l < 2; l++) {
            int idx = tid + l * NTHREADS;
            *(float4*)&sm[W3_OFF + idx * 4] = g3[idx];
        }
    }
    __syncthreads();

    // ---------------- Phase 2: h2 = relu(h1 @ W2 + b2)  [64,128]@[128,64] ----------------
    {
        const int rg = tid >> 4;        // rows rg*4..+3
        const int cg = tid & 15;        // cols cg*4..+3
        float acc[4][4];
        #pragma unroll
        for (int i = 0; i < 4; i++)
            #pragma unroll
            for (int j = 0; j < 4; j++) acc[i][j] = 0.f;

        #pragma unroll 4
        for (int k = 0; k < 128; k += 4) {
            float xs[4][4];
            #pragma unroll
            for (int i = 0; i < 4; i++) {
                float4 v = *(const float4*)&sm[H1_OFF + (rg * 4 + i) * H1LD + k];
                xs[i][0] = v.x; xs[i][1] = v.y; xs[i][2] = v.z; xs[i][3] = v.w;
            }
            #pragma unroll
            for (int q = 0; q < 4; q++) {
                float4 w = *(const float4*)&sm[W2_OFF + (k + q) * 64 + cg * 4];
                #pragma unroll
                for (int i = 0; i < 4; i++) {
                    float xq = xs[i][q];
                    acc[i][0] = fmaf(xq, w.x, acc[i][0]);
                    acc[i][1] = fmaf(xq, w.y, acc[i][1]);
                    acc[i][2] = fmaf(xq, w.z, acc[i][2]);
                    acc[i][3] = fmaf(xq, w.w, acc[i][3]);
                }
            }
        }
        float bb[4];
        #pragma unroll
        for (int j = 0; j < 4; j++) bb[j] = __ldg(&b2[cg * 4 + j]);
        #pragma unroll
        for (int i = 0; i < 4; i++) {
            float4 o;
            o.x = fmaxf(acc[i][0] + bb[0], 0.f);
            o.y = fmaxf(acc[i][1] + bb[1], 0.f);
            o.z = fmaxf(acc[i][2] + bb[2], 0.f);
            o.w = fmaxf(acc[i][3] + bb[3], 0.f);
            *(float4*)&sm[H2_OFF + (rg * 4 + i) * H2LD + cg * 4] = o;
        }
    }
    __syncthreads();

    // ---------------- Phase 3: h3 = relu(h2 @ W3 + b3)  [64,64]@[64,32] ----------------
    {
        const int rg = tid >> 3;        // rows rg*2..+1 (32 groups)
        const int cg = tid & 7;         // cols cg*4..+3 (8 groups)
        float acc[2][4];
        #pragma unroll
        for (int i = 0; i < 2; i++)
            #pragma unroll
            for (int j = 0; j < 4; j++) acc[i][j] = 0.f;

        #pragma unroll 4
        for (int k = 0; k < 64; k += 4) {
            float xs[2][4];
            #pragma unroll
            for (int i = 0; i < 2; i++) {
                float4 v = *(const float4*)&sm[H2_OFF + (rg * 2 + i) * H2LD + k];
                xs[i][0] = v.x; xs[i][1] = v.y; xs[i][2] = v.z; xs[i][3] = v.w;
            }
            #pragma unroll
            for (int q = 0; q < 4; q++) {
                float4 w = *(const float4*)&sm[W3_OFF + (k + q) * 32 + cg * 4];
                #pragma unroll
                for (int i = 0; i < 2; i++) {
                    float xq = xs[i][q];
                    acc[i][0] = fmaf(xq, w.x, acc[i][0]);
                    acc[i][1] = fmaf(xq, w.y, acc[i][1]);
                    acc[i][2] = fmaf(xq, w.z, acc[i][2]);
                    acc[i][3] = fmaf(xq, w.w, acc[i][3]);
                }
            }
        }
        float bb[4];
        #pragma unroll
        for (int j = 0; j < 4; j++) bb[j] = __ldg(&b3[cg * 4 + j]);
        #pragma unroll
        for (int i = 0; i < 2; i++) {
            float4 o;
            o.x = fmaxf(acc[i][0] + bb[0], 0.f);
            o.y = fmaxf(acc[i][1] + bb[1], 0.f);
            o.z = fmaxf(acc[i][2] + bb[2], 0.f);
            o.w = fmaxf(acc[i][3] + bb[3], 0.f);
            *(float4*)&sm[H3_OFF + (rg * 2 + i) * H3LD + cg * 4] = o;
        }
    }
    __syncthreads();

    // ---------------- Phase 4: final combine + sigmoid (one thread per row) ----------------
    if (tid < MROWS) {
        float dot = 0.f;
        #pragma unroll
        for (int k = 0; k < 32; k += 4) {
            float4 h = *(const float4*)&sm[H3_OFF + tid * H3LD + k];
            float4 w = *(const float4*)&sm[WO_OFF + k];
            dot = fmaf(h.x, w.x, dot);
            dot = fmaf(h.y, w.y, dot);
            dot = fmaf(h.z, w.z, dot);
            dot = fmaf(h.w, w.w, dot);
        }
        float logit = sm[LIN_OFF + tid] + __ldg(lin_b)
                    + sm[FM2_OFF + tid]
                    + dot + __ldg(bo) + __ldg(bias);
        out[r0 + tid] = 1.f / (1.f + expf(-logit));
    }
}

extern "C" void kernel_launch(void* const* d_in, const int* in_sizes, int n_in,
                              void* d_out, int out_size)
{
    (void)in_sizes; (void)n_in; (void)out_size;
    const float* x     = (const float*)d_in[0];
    const float* fm_w  = (const float*)d_in[1];
    const float* fm_b  = (const float*)d_in[2];
    const float* lin_w = (const float*)d_in[3];
    const float* lin_b = (const float*)d_in[4];
    const float* w1    = (const float*)d_in[5];
    const float* b1    = (const float*)d_in[6];
    const float* w2    = (const float*)d_in[7];
    const float* b2    = (const float*)d_in[8];
    const float* w3    = (const float*)d_in[9];
    const float* b3    = (const float*)d_in[10];
    const float* wo    = (const float*)d_in[11];
    const float* bo    = (const float*)d_in[12];
    const float* bias  = (const float*)d_in[13];

    const size_t smem_bytes = (size_t)SMEM_FLOATS * sizeof(float);
    cudaFuncSetAttribute(deepfm_fused_kernel,
                         cudaFuncAttributeMaxDynamicSharedMemorySize,
                         (int)smem_bytes);

    deepfm_fused_kernel<<<16384 / MROWS, NTHREADS, smem_bytes>>>(
        x, fm_w, fm_b, lin_w, lin_b, w1, b1, w2, b2, w3, b3, wo, bo, bias,
        (float*)d_out);
}